// round 17
// baseline (speedup 1.0000x reference)
#include <cuda_runtime.h>
#include <cstdint>

#define EMB_DIM  1024
#define LN_EPS   1e-5f
#define MAX_B    8192
#define MAX_R    5120      // prepass supports up to 5120 relations

// ---------------- device scratch (no allocation allowed) ----------------
__device__ int g_ids_is64;
__device__ int g_rows[MAX_B];       // batch indices sorted by relation id

// ---------------- prepass: ONE single-block kernel (validated R14) --------
__global__ __launch_bounds__(1024)
void prepass_kernel(const int* __restrict__ w, int n_ids, int batch, int R) {
    __shared__ int hist[MAX_R];              // counts, then scatter cursors
    __shared__ unsigned short sid[MAX_B];    // ids cached in smem
    __shared__ int wsum[32];
    const int t = threadIdx.x, lid = t & 31, wid = t >> 5;

    // dtype sniff: odd words of first <=512 words all zero <=> int64 (ids < 5000)
    const int lim = (n_ids < 512) ? n_ids : 512;
    int nz = 0;
    for (int i = 1 + 2 * t; i < lim; i += 2048) nz |= (w[i] != 0);
    const int is64 = (__syncthreads_or(nz) == 0);
    if (t == 0) g_ids_is64 = is64;

    for (int i = t; i < R; i += 1024) hist[i] = 0;
    __syncthreads();

    for (int b = t; b < batch; b += 1024) {
        const int id = is64 ? w[2 * b] : w[b];
        sid[b] = (unsigned short)id;
        atomicAdd(&hist[id], 1);
    }
    __syncthreads();

    // exclusive scan of hist: 5 elems/thread, warp-shuffle based
    const int base = t * 5;
    int loc[5];
    int s = 0;
#pragma unroll
    for (int i = 0; i < 5; ++i) {
        const int v = (base + i < R) ? hist[base + i] : 0;
        loc[i] = v; s += v;
    }
    int ss = s;
#pragma unroll
    for (int o = 1; o < 32; o <<= 1) {
        const int v = __shfl_up_sync(~0u, ss, o);
        if (lid >= o) ss += v;
    }
    if (lid == 31) wsum[wid] = ss;
    __syncthreads();
    if (t < 32) {
        const int v = wsum[t];
        int vv = v;
#pragma unroll
        for (int o = 1; o < 32; o <<= 1) {
            const int u = __shfl_up_sync(~0u, vv, o);
            if (t >= o) vv += u;
        }
        wsum[t] = vv - v;
    }
    __syncthreads();
    const int excl = wsum[wid] + (ss - s);
    {
        int r2 = excl;
#pragma unroll
        for (int i = 0; i < 5; ++i) {
            if (base + i < R) { hist[base + i] = r2; r2 += loc[i]; }
        }
    }
    __syncthreads();

    for (int b = t; b < batch; b += 1024) {
        const int pos = atomicAdd(&hist[sid[b]], 1);
        g_rows[pos] = b;
    }
}

// ---------------- main: TWO sorted batch rows per CTA ----------------
// If the pair shares a relation (common after sorting), each T float4 is
// loaded once and feeds both rows' dots -> T traffic through L1 is halved
// for that pair. Otherwise two sequential passes (same cost as 1 row/CTA).
__global__ __launch_bounds__(256)
void wproj_pair_kernel(
    const float* __restrict__ ent_emb,   // [B, 1024]
    const void*  __restrict__ proj_ids,  // [B] int32 or int64
    const float* __restrict__ tran,      // [R, 1024, 16]
    const float* __restrict__ bias,      // [R, 1024]
    const float* __restrict__ ln_w,      // [1024]
    const float* __restrict__ ln_b,      // [1024]
    float*       __restrict__ out)       // [B, 1024]
{
    const int k = blockIdx.x;
    const int t = threadIdx.x;

    const int b0 = g_rows[2 * k];
    const int b1 = g_rows[2 * k + 1];

    __shared__ float4 Es0[256], Es1[256];          // 2x4 KB entity rows
    __shared__ float  Xs0[EMB_DIM], Xs1[EMB_DIM];  // 2x4 KB pure-dot values
    __shared__ float  rA[8], r2A[8], rB[8], r2B[8];

    Es0[t] = __ldg(reinterpret_cast<const float4*>(ent_emb + (size_t)b0 * EMB_DIM) + t);
    Es1[t] = __ldg(reinterpret_cast<const float4*>(ent_emb + (size_t)b1 * EMB_DIM) + t);
    __syncthreads();

    long long rel0, rel1;
    if (g_ids_is64) {
        rel0 = reinterpret_cast<const long long*>(proj_ids)[b0];
        rel1 = reinterpret_cast<const long long*>(proj_ids)[b1];
    } else {
        rel0 = (long long)reinterpret_cast<const int*>(proj_ids)[b0];
        rel1 = (long long)reinterpret_cast<const int*>(proj_ids)[b1];
    }

    const float4* T0 = reinterpret_cast<const float4*>(tran) + (size_t)rel0 * 4096;
    const float4* T1 = reinterpret_cast<const float4*>(tran) + (size_t)rel1 * 4096;

    const int q  = t & 3;    // quad lane: k-chunk [4q, 4q+4)
    const int rr = t >> 2;   // base row (0..63)

    if (rel0 == rel1) {      // block-uniform branch (rel0/rel1 CTA-wide values)
        // fused: one T load feeds both rows
#pragma unroll
        for (int j = 0; j < 16; ++j) {
            const int r = rr + 64 * j;
            const float4 tv  = __ldg(T0 + r * 4 + q);      // warp: 512B contiguous
            const float4 ev0 = Es0[(r >> 4) * 4 + q];
            const float4 ev1 = Es1[(r >> 4) * 4 + q];
            float a0 = tv.x * ev0.x + tv.y * ev0.y + tv.z * ev0.z + tv.w * ev0.w;
            float a1 = tv.x * ev1.x + tv.y * ev1.y + tv.z * ev1.z + tv.w * ev1.w;
            a0 += __shfl_xor_sync(0xffffffffu, a0, 1);
            a0 += __shfl_xor_sync(0xffffffffu, a0, 2);
            a1 += __shfl_xor_sync(0xffffffffu, a1, 1);
            a1 += __shfl_xor_sync(0xffffffffu, a1, 2);
            if (q == 0) { Xs0[r] = a0; Xs1[r] = a1; }
        }
    } else {
        // two sequential passes
#pragma unroll
        for (int j = 0; j < 16; ++j) {
            const int r = rr + 64 * j;
            const float4 tv  = __ldg(T0 + r * 4 + q);
            const float4 ev0 = Es0[(r >> 4) * 4 + q];
            float a0 = tv.x * ev0.x + tv.y * ev0.y + tv.z * ev0.z + tv.w * ev0.w;
            a0 += __shfl_xor_sync(0xffffffffu, a0, 1);
            a0 += __shfl_xor_sync(0xffffffffu, a0, 2);
            if (q == 0) Xs0[r] = a0;
        }
#pragma unroll
        for (int j = 0; j < 16; ++j) {
            const int r = rr + 64 * j;
            const float4 tv  = __ldg(T1 + r * 4 + q);
            const float4 ev1 = Es1[(r >> 4) * 4 + q];
            float a1 = tv.x * ev1.x + tv.y * ev1.y + tv.z * ev1.z + tv.w * ev1.w;
            a1 += __shfl_xor_sync(0xffffffffu, a1, 1);
            a1 += __shfl_xor_sync(0xffffffffu, a1, 2);
            if (q == 0) Xs1[r] = a1;
        }
    }
    __syncthreads();   // Xs0/Xs1 complete

    // fused tail: bias, stats for both rows in one reduction round
    const float4 d0 = reinterpret_cast<const float4*>(Xs0)[t];
    const float4 d1 = reinterpret_cast<const float4*>(Xs1)[t];
    const float4 v0 = __ldg(reinterpret_cast<const float4*>(bias + (size_t)rel0 * EMB_DIM) + t);
    const float4 v1 = __ldg(reinterpret_cast<const float4*>(bias + (size_t)rel1 * EMB_DIM) + t);
    float4 xa, xb;
    xa.x = d0.x + v0.x; xa.y = d0.y + v0.y; xa.z = d0.z + v0.z; xa.w = d0.w + v0.w;
    xb.x = d1.x + v1.x; xb.y = d1.y + v1.y; xb.z = d1.z + v1.z; xb.w = d1.w + v1.w;

    float sa  = xa.x + xa.y + xa.z + xa.w;
    float s2a = xa.x * xa.x + xa.y * xa.y + xa.z * xa.z + xa.w * xa.w;
    float sb  = xb.x + xb.y + xb.z + xb.w;
    float s2b = xb.x * xb.x + xb.y * xb.y + xb.z * xb.z + xb.w * xb.w;
#pragma unroll
    for (int o = 16; o > 0; o >>= 1) {
        sa  += __shfl_xor_sync(0xffffffffu, sa,  o);
        s2a += __shfl_xor_sync(0xffffffffu, s2a, o);
        sb  += __shfl_xor_sync(0xffffffffu, sb,  o);
        s2b += __shfl_xor_sync(0xffffffffu, s2b, o);
    }
    const int wid = t >> 5, lid = t & 31;
    if (lid == 0) { rA[wid] = sa; r2A[wid] = s2a; rB[wid] = sb; r2B[wid] = s2b; }
    __syncthreads();

    float SA = 0.f, S2A = 0.f, SB = 0.f, S2B = 0.f;
#pragma unroll
    for (int i = 0; i < 8; ++i) { SA += rA[i]; S2A += r2A[i]; SB += rB[i]; S2B += r2B[i]; }

    const float meanA = SA  * (1.0f / 1024.0f);
    const float varA  = S2A * (1.0f / 1024.0f) - meanA * meanA;
    const float rstdA = rsqrtf(varA + LN_EPS);
    const float meanB = SB  * (1.0f / 1024.0f);
    const float varB  = S2B * (1.0f / 1024.0f) - meanB * meanB;
    const float rstdB = rsqrtf(varB + LN_EPS);

    const float4 w = __ldg(reinterpret_cast<const float4*>(ln_w) + t);
    const float4 c = __ldg(reinterpret_cast<const float4*>(ln_b) + t);

    float4 oa, ob;
    oa.x = (xa.x - meanA) * rstdA * w.x + c.x;
    oa.y = (xa.y - meanA) * rstdA * w.y + c.y;
    oa.z = (xa.z - meanA) * rstdA * w.z + c.z;
    oa.w = (xa.w - meanA) * rstdA * w.w + c.w;
    ob.x = (xb.x - meanB) * rstdB * w.x + c.x;
    ob.y = (xb.y - meanB) * rstdB * w.y + c.y;
    ob.z = (xb.z - meanB) * rstdB * w.z + c.z;
    ob.w = (xb.w - meanB) * rstdB * w.w + c.w;
    reinterpret_cast<float4*>(out + (size_t)b0 * EMB_DIM)[t] = oa;
    reinterpret_cast<float4*>(out + (size_t)b1 * EMB_DIM)[t] = ob;
}

extern "C" void kernel_launch(void* const* d_in, const int* in_sizes, int n_in,
                              void* d_out, int out_size) {
    const float* ent_emb = (const float*)d_in[0];
    const void*  ids     = d_in[1];
    const float* tran    = (const float*)d_in[2];
    const float* bias    = (const float*)d_in[3];
    const float* ln_w    = (const float*)d_in[4];
    const float* ln_b    = (const float*)d_in[5];
    float*       out     = (float*)d_out;

    const int batch = in_sizes[0] / EMB_DIM;               // 8192 (even)
    const int R     = in_sizes[2] / (EMB_DIM * 16);        // 5000
    const int n_ids = in_sizes[1];

    prepass_kernel<<<1, 1024>>>((const int*)ids, n_ids, batch, R);
    wproj_pair_kernel<<<batch / 2, 256>>>(ent_emb, ids, tran, bias, ln_w, ln_b, out);
}